// round 4
// baseline (speedup 1.0000x reference)
#include <cuda_runtime.h>

#define NF  256
#define GS  16
#define NG  16
#define HWS 3136        // 56*56
#define MB  32
#define NTOT (MB*HWS)   // 100352
#define NPAIR 136       // 16*17/2
#define NF2  (HWS/2)    // 1568 float2 positions
#define NF4  (HWS/4)    // 784  float4 positions
#define SS   4          // spatial split
#define CH2  (NF2/SS)   // 392 float2 positions per stats chunk
#define CH4  (NF4/SS)   // 196 float4 positions per whiten chunk
#define NPART (MB*SS)   // 128 partial sets per group

typedef unsigned long long u64;

// Scratch (device globals: no allocation allowed)
__device__ float g_part[NG][NPART][152]; // per (g,m,z): 136 gram pairs + 16 channel sums
__device__ float g_W[NG][NPAIR];         // lower-tri inv(chol(Sigma)), k = i*(i+1)/2 + j
__device__ float g_b[NG][GS];            // b_i = sum_{j<=i} W_ij * mu_j

// ---------------------------------------------------------------------------
// packed f32x2 helpers
// ---------------------------------------------------------------------------
__device__ __forceinline__ u64 ffma2(u64 a, u64 b, u64 c) {
    u64 d;
    asm("fma.rn.f32x2 %0, %1, %2, %3;" : "=l"(d) : "l"(a), "l"(b), "l"(c));
    return d;
}
__device__ __forceinline__ float2 u2f2(u64 v) {
    float2 f;
    asm("mov.b64 {%0, %1}, %2;" : "=f"(f.x), "=f"(f.y) : "l"(v));
    return f;
}

// ---------------------------------------------------------------------------
// Kernel 1: per-group raw Gram + channel sums over one spatial chunk.
// Grid (g=16, m=32, z=4), 128 threads. Warp W owns pairs [34W,34W+34)
// (compile-time pruned) and channel sums 4W..4W+3. ~12 iters/warp.
// ---------------------------------------------------------------------------
template<int W>
__device__ __forceinline__ void accum_warp(const float* __restrict__ base,
                                           int lane, int z,
                                           float* __restrict__ part) {
    u64 acc[34];
    float s[4];
#pragma unroll
    for (int k = 0; k < 34; k++) acc[k] = 0ull;
#pragma unroll
    for (int c = 0; c < 4; c++) s[c] = 0.f;

    const int f0 = z * CH2;
    const int f1 = f0 + CH2;
    for (int f = f0 + lane; f < f1; f += 32) {
        u64 v[GS];
#pragma unroll
        for (int c = 0; c < GS; c++)
            v[c] = ((const u64*)(base + (size_t)c * HWS))[f];
#pragma unroll
        for (int i = 0; i < GS; i++)
#pragma unroll
            for (int j = 0; j <= i; j++) {
                const int k = i * (i + 1) / 2 + j;
                if (k >= 34 * W && k < 34 * W + 34)
                    acc[k - 34 * W] = ffma2(v[i], v[j], acc[k - 34 * W]);
            }
#pragma unroll
        for (int c = 0; c < 4; c++) {
            float2 f2 = u2f2(v[4 * W + c]);
            s[c] += f2.x + f2.y;
        }
    }

    // warp reduce + write partials (pairs disjoint per warp)
#pragma unroll
    for (int k = 0; k < 34; k++) {
        float2 f2 = u2f2(acc[k]);
        float gsum = f2.x + f2.y;
#pragma unroll
        for (int sh = 16; sh > 0; sh >>= 1)
            gsum += __shfl_xor_sync(0xFFFFFFFFu, gsum, sh);
        if (lane == 0) part[34 * W + k] = gsum;
    }
#pragma unroll
    for (int c = 0; c < 4; c++) {
        float v = s[c];
#pragma unroll
        for (int sh = 16; sh > 0; sh >>= 1)
            v += __shfl_xor_sync(0xFFFFFFFFu, v, sh);
        if (lane == 0) part[136 + 4 * W + c] = v;
    }
}

__global__ __launch_bounds__(128) void stats_kernel(const float* __restrict__ x) {
    const int g = blockIdx.x;
    const int m = blockIdx.y;
    const int z = blockIdx.z;
    const float* base = x + ((size_t)m * NF + (size_t)g * GS) * HWS;
    const int wid  = threadIdx.x >> 5;
    const int lane = threadIdx.x & 31;
    float* part = g_part[g][m * SS + z];
    switch (wid) {
        case 0: accum_warp<0>(base, lane, z, part); break;
        case 1: accum_warp<1>(base, lane, z, part); break;
        case 2: accum_warp<2>(base, lane, z, part); break;
        case 3: accum_warp<3>(base, lane, z, part); break;
    }
}

// ---------------------------------------------------------------------------
// Kernel 2: reduce partials -> sigma -> Cholesky -> inverse -> (W, b).
// One warp per group (512 threads), fp32 throughout.
// ---------------------------------------------------------------------------
__global__ __launch_bounds__(512) void solve_kernel() {
    __shared__ float a [NG][GS][GS + 1];   // sigma, then Cholesky T in lower part
    __shared__ float w [NG][GS][GS + 1];   // T^{-1}
    __shared__ float mu[NG][GS];
    __shared__ float red[NG][152];         // reduced partials

    const int g    = threadIdx.x >> 5;
    const int lane = threadIdx.x & 31;
    const float n = (float)NTOT;

    // reduce the NPART partial sets: each lane owns ~5 of 152 entries,
    // 4-way MLP over the chunk axis.
    for (int e = lane; e < 152; e += 32) {
        float s0 = 0.f, s1 = 0.f, s2 = 0.f, s3 = 0.f;
        for (int c = 0; c < NPART; c += 4) {
            s0 += g_part[g][c + 0][e];
            s1 += g_part[g][c + 1][e];
            s2 += g_part[g][c + 2][e];
            s3 += g_part[g][c + 3][e];
        }
        red[g][e] = (s0 + s1) + (s2 + s3);
    }
    __syncwarp();

    if (lane < GS) mu[g][lane] = red[g][136 + lane] / n;
    __syncwarp();

    // sigma (both triangles)
    for (int idx = lane; idx < 256; idx += 32) {
        const int i = idx >> 4, j = idx & 15;
        const int ii = i > j ? i : j;
        const int jj = i > j ? j : i;
        float G = red[g][ii * (ii + 1) / 2 + jj];
        float sh = (G - n * mu[g][i] * mu[g][j]) / (n - 1.0f);
        a[g][i][j] = (1.0f - 1e-6f) * sh + ((i == j) ? 1e-6f : 0.0f);
    }
    __syncwarp();

    // Cholesky in-place (lower), lane i owns row i
    for (int j = 0; j < GS; j++) {
        if (lane == j) a[g][j][j] = sqrtf(a[g][j][j]);
        __syncwarp();
        const float tjj = a[g][j][j];
        if (lane > j && lane < GS) a[g][lane][j] /= tjj;
        __syncwarp();
        if (lane > j && lane < GS) {
            const float lij = a[g][lane][j];
            for (int k = j + 1; k <= lane; k++)
                a[g][lane][k] -= lij * a[g][k][j];
        }
        __syncwarp();
    }

    // W = T^{-1}: lane j computes column j by forward substitution
    if (lane < GS) {
        const int j = lane;
        w[g][j][j] = 1.0f / a[g][j][j];
        for (int i = j + 1; i < GS; i++) {
            float s = 0.f;
            for (int k = j; k < i; k++) s += a[g][i][k] * w[g][k][j];
            w[g][i][j] = -s / a[g][i][i];
        }
        for (int i = j; i < GS; i++)
            g_W[g][i * (i + 1) / 2 + j] = w[g][i][j];
    }
    __syncwarp();

    // b_i = sum_{j<=i} W_ij * mu_j
    if (lane < GS) {
        const int i = lane;
        float b = 0.f;
        for (int j = 0; j <= i; j++) b += w[g][i][j] * mu[g][j];
        g_b[g][i] = b;
    }
}

// ---------------------------------------------------------------------------
// Kernel 3: y = W*x - b (triangular). Grid (g=16, m=32, z=4), 128 threads,
// 196 float4-positions per block. Immediate stores keep regs ~100.
// ---------------------------------------------------------------------------
__global__ __launch_bounds__(128, 4) void whiten_kernel(const float* __restrict__ x,
                                                        float* __restrict__ out) {
    const int g = blockIdx.x;
    const int m = blockIdx.y;
    const int z = blockIdx.z;

    __shared__ float sW[NPAIR];
    __shared__ float sb[GS];
    for (int i = threadIdx.x; i < NPAIR + GS; i += 128) {
        if (i < NPAIR) sW[i] = g_W[g][i];
        else           sb[i - NPAIR] = g_b[g][i - NPAIR];
    }
    __syncthreads();

    const size_t base = ((size_t)m * NF + (size_t)g * GS) * HWS;
    const int f0 = z * CH4;
    const int f1 = f0 + CH4;

    for (int f = f0 + threadIdx.x; f < f1; f += 128) {
        float4 v[GS];
#pragma unroll
        for (int c = 0; c < GS; c++)
            v[c] = ((const float4*)(x + base + (size_t)c * HWS))[f];

#pragma unroll
        for (int i = 0; i < GS; i++) {
            const float b = sb[i];
            float4 y = make_float4(-b, -b, -b, -b);
#pragma unroll
            for (int j = 0; j <= i; j++) {
                const float w = sW[i * (i + 1) / 2 + j];
                y.x = fmaf(w, v[j].x, y.x);
                y.y = fmaf(w, v[j].y, y.y);
                y.z = fmaf(w, v[j].z, y.z);
                y.w = fmaf(w, v[j].w, y.w);
            }
            ((float4*)(out + base + (size_t)i * HWS))[f] = y;
        }
    }
}

// ---------------------------------------------------------------------------
extern "C" void kernel_launch(void* const* d_in, const int* in_sizes, int n_in,
                              void* d_out, int out_size) {
    const float* x = (const float*)d_in[0];
    float* out = (float*)d_out;

    dim3 grid(NG, MB, SS);
    stats_kernel<<<grid, 128>>>(x);
    solve_kernel<<<1, 512>>>();
    whiten_kernel<<<grid, 128>>>(x, out);
}